// round 16
// baseline (speedup 1.0000x reference)
#include <cuda_runtime.h>

// ---------------------------------------------------------------------------
// LSTMModel: 4-layer LSTM (H=50) over B=1024, T=512, IN=7, + FC(25) + FC(1).
// R10 = R9 with the prefetch-coverage bug fixed: the xp(t+1) smem stage is
// GG*NB/4 = 400 ulonglong2, needing 7 chunks of 64 loader threads (R9 only
// copied 256 -> gates 128..199 read stale xp).
// Fused layer kernel: warps 0-6 recurrence (dup'd-Whh fma.f32x2, acc init
// from smem-staged xp incl. bias); warps 8-14 produce NEXT layer's xp from
// h(t-1) in idle issue slots; 64 spare threads prefetch xp(t+1) GMEM->smem.
// ---------------------------------------------------------------------------

#define TT  512
#define BB  1024
#define HH  50
#define GG  200
#define NB  8
#define NCTA (BB / NB)    // 128
#define IN0 7
#define FC1 25
#define NLD ((GG * NB / 4 + 63) / 64)   // 7 chunks of 64 ulonglong2

// xp ping-pong: [t][ct][g][b'] packed
__device__ float g_xpA[(size_t)TT * NCTA * GG * NB];
__device__ float g_xpB[(size_t)TT * NCTA * GG * NB];
__device__ float g_hlast[BB * HH];

__device__ __forceinline__ float sigmf(float x) {
    return __fdividef(1.0f, 1.0f + __expf(-x));
}
__device__ __forceinline__ float tanhfast(float x) {
    float e = __expf(2.0f * x);
    return 1.0f - __fdividef(2.0f, e + 1.0f);
}

#define FMA2(acc, w, h) \
    asm("fma.rn.f32x2 %0, %1, %2, %0;" : "+l"(acc) : "l"(w), "l"(h))
#define DUP2(out, w) \
    asm("mov.b64 %0, {%1, %1};" : "=l"(out) : "f"(w))

// ---------------------------------------------------------------------------
// Layer-0 xp GEMM: xp[t][ct][g][b'] = bias0[g] + sum_k x[b][t][k] * Wih0[g][k]
// ---------------------------------------------------------------------------
__global__ void __launch_bounds__(256, 2) xp0_gemm_kernel(
    const float* __restrict__ x,
    const float* __restrict__ Wih,   // [GG][IN0]
    const float* __restrict__ bih,
    const float* __restrict__ bhh,
    float* __restrict__ xp)
{
    constexpr int TCH = 64;

    __shared__ __align__(16) float sh[2][IN0][NB];

    const int tid = threadIdx.x;
    const int ct  = blockIdx.x & (NCTA - 1);
    const int t0  = (int)(blockIdx.x >> 7) * TCH;
    const int b0  = ct * NB;

    const int g = (tid < GG) ? tid : (GG - 1);
    unsigned long long wd[IN0], bgd;
    if (tid < 224) {
#pragma unroll
        for (int k = 0; k < IN0; k++) DUP2(wd[k], Wih[g * IN0 + k]);
        DUP2(bgd, bih[g] + bhh[g]);
    }

    const int sk = tid >> 3, sb = tid & 7;           // stager: tid < 56
    const bool stager = (tid < IN0 * NB);

    if (stager)
        sh[0][sk][sb] = x[(size_t)(b0 + sb) * TT * IN0 + (size_t)t0 * IN0 + sk];
    __syncthreads();

    int buf = 0;
    for (int t = t0; t < t0 + TCH; t++) {
        const bool hn = (t + 1 < t0 + TCH);
        float pf = 0.0f;
        if (stager && hn)
            pf = x[(size_t)(b0 + sb) * TT * IN0 + (size_t)(t + 1) * IN0 + sk];

        if (tid < 224) {
            unsigned long long a[4] = {bgd, bgd, bgd, bgd};
#pragma unroll
            for (int k = 0; k < IN0; k++) {
                ulonglong2 v0 = *(const ulonglong2*)&sh[buf][k][0];
                ulonglong2 v1 = *(const ulonglong2*)&sh[buf][k][4];
                FMA2(a[0], wd[k], v0.x);
                FMA2(a[1], wd[k], v0.y);
                FMA2(a[2], wd[k], v1.x);
                FMA2(a[3], wd[k], v1.y);
            }
            if (tid < GG) {
                size_t base = (((size_t)t * NCTA + ct) * GG + g) * NB;
                ulonglong2 o0; o0.x = a[0]; o0.y = a[1];
                ulonglong2 o1; o1.x = a[2]; o1.y = a[3];
                *(ulonglong2*)&xp[base]     = o0;
                *(ulonglong2*)&xp[base + 4] = o1;
            }
        }
        if (stager && hn) sh[buf ^ 1][sk][sb] = pf;
        __syncthreads();
        buf ^= 1;
    }
}

// ---------------------------------------------------------------------------
// Fused layer: recurrence (warps 0-6) + next-layer xp production (warps 8-14)
// + xp(t+1) prefetch (spare 64 threads). xp_cur already contains the bias.
// ---------------------------------------------------------------------------
__global__ void __launch_bounds__(512, 1) lstm_fused_kernel(
    const float* __restrict__ xp_cur,
    float* __restrict__ xp_next,
    int has_next,
    const float* __restrict__ Wih_next,  // [GG][HH]
    const float* __restrict__ bih_next,
    const float* __restrict__ bhh_next,
    const float* __restrict__ Whh)       // [GG][HH]
{
    __shared__ __align__(16) float sh_h[HH][NB];       // h(t-1)
    __shared__ __align__(16) float sh_g[GG][NB];       // gates
    __shared__ __align__(16) float sh_xp[2][GG][NB];   // staged xp (w/ bias)

    const int tid = threadIdx.x;
    const int ct  = blockIdx.x;
    const int b0  = ct * NB;

    const bool is_gate = (tid < 224);
    const bool is_xp   = (tid >= 256 && tid < 480);
    // loaders: tid in [224,256) U [480,512) -> idx 0..63
    const bool is_ld = (!is_gate && !is_xp);
    const int  ldx   = (tid < 256) ? (tid - 224) : (tid - 480 + 32);

    // ---- gate role registers
    const int g = is_gate ? ((tid < GG) ? tid : (GG - 1)) : 0;
    unsigned long long wd[HH];
    if (is_gate) {
#pragma unroll
        for (int k = 0; k < HH; k++) DUP2(wd[k], Whh[g * HH + k]);
    }
    // update-thread state: tid<200 owns (jj, rows bu and bu+4)
    const int jj = tid >> 2;
    const int bu = tid & 3;
    float c0 = 0.0f, c1 = 0.0f;

    // ---- xp-next role registers
    const int xg = is_xp ? (((tid - 256) < GG) ? (tid - 256) : (GG - 1)) : 0;
    unsigned long long wn[HH], bnd = 0ull;
    if (is_xp && has_next) {
#pragma unroll
        for (int k = 0; k < HH; k++) DUP2(wn[k], Wih_next[xg * HH + k]);
        DUP2(bnd, bih_next[xg] + bhh_next[xg]);
    }

    // ---- init: h0 = 0; stage xp(t=0)
    for (int i = tid; i < HH * NB; i += 512)
        (&sh_h[0][0])[i] = 0.0f;
    {
        const ulonglong2* src = (const ulonglong2*)
            &xp_cur[(((size_t)0 * NCTA + ct) * GG) * NB];
        ulonglong2* dst = (ulonglong2*)&sh_xp[0][0][0];
        for (int i = tid; i < GG * NB / 4; i += 512) dst[i] = src[i];
    }
    __syncthreads();

    int buf = 0;
    for (int t = 0; t < TT; t++) {
        // =========== phase A (reads sh_h = h(t-1), sh_xp[buf] = xp(t)) =====
        ulonglong2 pf[NLD];
        if (is_gate) {
            ulonglong2 x01 = *(const ulonglong2*)&sh_xp[buf][g][0];
            ulonglong2 x23 = *(const ulonglong2*)&sh_xp[buf][g][4];
            unsigned long long a0 = x01.x, a1 = x01.y, a2 = x23.x, a3 = x23.y;
#pragma unroll
            for (int k = 0; k < HH; k++) {
                ulonglong2 h0 = *(const ulonglong2*)&sh_h[k][0];
                ulonglong2 h1 = *(const ulonglong2*)&sh_h[k][4];
                FMA2(a0, wd[k], h0.x);
                FMA2(a1, wd[k], h0.y);
                FMA2(a2, wd[k], h1.x);
                FMA2(a3, wd[k], h1.y);
            }
            if (tid < GG) {
                ulonglong2 o0; o0.x = a0; o0.y = a1;
                ulonglong2 o1; o1.x = a2; o1.y = a3;
                *(ulonglong2*)&sh_g[g][0] = o0;
                *(ulonglong2*)&sh_g[g][4] = o1;
            }
        } else if (is_xp) {
            if (has_next && t > 0) {
                unsigned long long a[4] = {bnd, bnd, bnd, bnd};
#pragma unroll
                for (int k = 0; k < HH; k++) {
                    ulonglong2 h0 = *(const ulonglong2*)&sh_h[k][0];
                    ulonglong2 h1 = *(const ulonglong2*)&sh_h[k][4];
                    FMA2(a[0], wn[k], h0.x);
                    FMA2(a[1], wn[k], h0.y);
                    FMA2(a[2], wn[k], h1.x);
                    FMA2(a[3], wn[k], h1.y);
                }
                if (tid - 256 < GG) {
                    size_t base = (((size_t)(t - 1) * NCTA + ct) * GG + xg) * NB;
                    ulonglong2 o0; o0.x = a[0]; o0.y = a[1];
                    ulonglong2 o1; o1.x = a[2]; o1.y = a[3];
                    *(ulonglong2*)&xp_next[base]     = o0;
                    *(ulonglong2*)&xp_next[base + 4] = o1;
                }
            }
        } else {
            // loaders: fetch xp(t+1) from global (ALL 400 ulonglong2)
            if (t + 1 < TT) {
                const ulonglong2* src = (const ulonglong2*)
                    &xp_cur[(((size_t)(t + 1) * NCTA + ct) * GG) * NB];
#pragma unroll
                for (int j = 0; j < NLD; j++) {
                    int i = ldx + j * 64;
                    if (i < GG * NB / 4) pf[j] = src[i];
                }
            }
        }
        __syncthreads();

        // =========== phase B: cell update + park prefetched xp ==============
        if (tid < GG) {
#pragma unroll
            for (int q = 0; q < 2; q++) {
                int b = bu + 4 * q;
                float ig = sigmf(sh_g[jj][b]);
                float fg = sigmf(sh_g[HH + jj][b]);
                float gg = tanhfast(sh_g[2 * HH + jj][b]);
                float og = sigmf(sh_g[3 * HH + jj][b]);
                float& c = q ? c1 : c0;
                c = fg * c + ig * gg;
                float h = og * tanhfast(c);
                sh_h[jj][b] = h;
                if (t == TT - 1) g_hlast[(b0 + b) * HH + jj] = h;
            }
        } else if (is_ld && t + 1 < TT) {
            ulonglong2* dst = (ulonglong2*)&sh_xp[buf ^ 1][0][0];
#pragma unroll
            for (int j = 0; j < NLD; j++) {
                int i = ldx + j * 64;
                if (i < GG * NB / 4) dst[i] = pf[j];
            }
        }
        __syncthreads();
        buf ^= 1;
    }

    // =========== epilogue: xp_next for h(TT-1) ==============================
    if (is_xp && has_next) {
        unsigned long long a[4] = {bnd, bnd, bnd, bnd};
#pragma unroll
        for (int k = 0; k < HH; k++) {
            ulonglong2 h0 = *(const ulonglong2*)&sh_h[k][0];
            ulonglong2 h1 = *(const ulonglong2*)&sh_h[k][4];
            FMA2(a[0], wn[k], h0.x);
            FMA2(a[1], wn[k], h0.y);
            FMA2(a[2], wn[k], h1.x);
            FMA2(a[3], wn[k], h1.y);
        }
        if (tid - 256 < GG) {
            size_t base = (((size_t)(TT - 1) * NCTA + ct) * GG + xg) * NB;
            ulonglong2 o0; o0.x = a[0]; o0.y = a[1];
            ulonglong2 o1; o1.x = a[2]; o1.y = a[3];
            *(ulonglong2*)&xp_next[base]     = o0;
            *(ulonglong2*)&xp_next[base + 4] = o1;
        }
    }
}

// ---------------------------------------------------------------------------
__global__ void fc_head_kernel(const float* __restrict__ W1,
                               const float* __restrict__ b1,
                               const float* __restrict__ W2,
                               const float* __restrict__ b2,
                               float* __restrict__ out)
{
    __shared__ float sW1[FC1 * HH];
    __shared__ float sW2[FC1];
    __shared__ float sb1[FC1];

    int tid = threadIdx.x;
    for (int i = tid; i < FC1 * HH; i += 256) sW1[i] = W1[i];
    if (tid < FC1) { sW2[tid] = W2[tid]; sb1[tid] = b1[tid]; }
    __syncthreads();

    int b = blockIdx.x * blockDim.x + tid;
    if (b < BB) {
        const float* h = &g_hlast[b * HH];
        float hreg[HH];
#pragma unroll
        for (int k = 0; k < HH; k++) hreg[k] = h[k];
        float o = b2[0];
#pragma unroll
        for (int j = 0; j < FC1; j++) {
            float a = sb1[j];
#pragma unroll
            for (int k = 0; k < HH; k++) a += sW1[j * HH + k] * hreg[k];
            o += sW2[j] * fmaxf(a, 0.0f);
        }
        out[b] = o;
    }
}

// ---------------------------------------------------------------------------
extern "C" void kernel_launch(void* const* d_in, const int* in_sizes, int n_in,
                              void* d_out, int out_size)
{
    const float* x    = (const float*)d_in[0];
    const float* Wih0 = (const float*)d_in[1];
    const float* Whh0 = (const float*)d_in[2];
    const float* bih0 = (const float*)d_in[3];
    const float* bhh0 = (const float*)d_in[4];
    const float* Wih1 = (const float*)d_in[5];
    const float* Whh1 = (const float*)d_in[6];
    const float* bih1 = (const float*)d_in[7];
    const float* bhh1 = (const float*)d_in[8];
    const float* Wih2 = (const float*)d_in[9];
    const float* Whh2 = (const float*)d_in[10];
    const float* bih2 = (const float*)d_in[11];
    const float* bhh2 = (const float*)d_in[12];
    const float* Wih3 = (const float*)d_in[13];
    const float* Whh3 = (const float*)d_in[14];
    const float* bih3 = (const float*)d_in[15];
    const float* bhh3 = (const float*)d_in[16];
    const float* W1   = (const float*)d_in[17];
    const float* b1   = (const float*)d_in[18];
    const float* W2   = (const float*)d_in[19];
    const float* b2   = (const float*)d_in[20];
    float* out = (float*)d_out;

    static float* xpA = nullptr;
    static float* xpB = nullptr;
    if (!xpA) cudaGetSymbolAddress((void**)&xpA, g_xpA);
    if (!xpB) cudaGetSymbolAddress((void**)&xpB, g_xpB);

    // layer-0 xp from external input (includes layer-0 bias)
    xp0_gemm_kernel<<<NCTA * (TT / 64), 256>>>(x, Wih0, bih0, bhh0, xpA);

    // fused layers: recurrence + next-layer xp production
    lstm_fused_kernel<<<NCTA, 512>>>(xpA, xpB, 1, Wih1, bih1, bhh1, Whh0);
    lstm_fused_kernel<<<NCTA, 512>>>(xpB, xpA, 1, Wih2, bih2, bhh2, Whh1);
    lstm_fused_kernel<<<NCTA, 512>>>(xpA, xpB, 1, Wih3, bih3, bhh3, Whh2);
    lstm_fused_kernel<<<NCTA, 512>>>(xpB, xpA, 0, Whh3, bih3, bhh3, Whh3);

    fc_head_kernel<<<(BB + 255) / 256, 256>>>(W1, b1, W2, b2, out);
}

// round 17
// speedup vs baseline: 2.3208x; 2.3208x over previous
#include <cuda_runtime.h>

// ---------------------------------------------------------------------------
// LSTMModel: 4-layer LSTM (H=50) over B=1024, T=512, IN=7, + FC(25) + FC(1).
// R11 = R10 with the register-spill fix: gate role (warps 0-6, Whh) and
// xp-next role (warps 7-13, Wih_next) now share ONE unified dup'd weight
// array w[50] loaded from a role-dependent pointer, and run the SAME
// FMA2 main loop (out = W . h(t-1) + init). Only init source and output
// destination differ. Loaders (warps 14-15) prefetch xp(t+1) GMEM->smem
// (all 400 ulonglong2 -- the R10 fix). No dual weight arrays -> ~115 regs,
// no local-memory spills.
// ---------------------------------------------------------------------------

#define TT  512
#define BB  1024
#define HH  50
#define GG  200
#define NB  8
#define NCTA (BB / NB)    // 128
#define IN0 7
#define FC1 25
#define NLD ((GG * NB / 4 + 63) / 64)   // 7 chunks of 64 ulonglong2

// xp ping-pong: [t][ct][g][b'] packed
__device__ float g_xpA[(size_t)TT * NCTA * GG * NB];
__device__ float g_xpB[(size_t)TT * NCTA * GG * NB];
__device__ float g_hlast[BB * HH];

__device__ __forceinline__ float sigmf(float x) {
    return __fdividef(1.0f, 1.0f + __expf(-x));
}
__device__ __forceinline__ float tanhfast(float x) {
    float e = __expf(2.0f * x);
    return 1.0f - __fdividef(2.0f, e + 1.0f);
}

#define FMA2(acc, w, h) \
    asm("fma.rn.f32x2 %0, %1, %2, %0;" : "+l"(acc) : "l"(w), "l"(h))
#define DUP2(out, w) \
    asm("mov.b64 %0, {%1, %1};" : "=l"(out) : "f"(w))

// ---------------------------------------------------------------------------
// Layer-0 xp GEMM: xp[t][ct][g][b'] = bias0[g] + sum_k x[b][t][k] * Wih0[g][k]
// ---------------------------------------------------------------------------
__global__ void __launch_bounds__(256, 2) xp0_gemm_kernel(
    const float* __restrict__ x,
    const float* __restrict__ Wih,   // [GG][IN0]
    const float* __restrict__ bih,
    const float* __restrict__ bhh,
    float* __restrict__ xp)
{
    constexpr int TCH = 64;

    __shared__ __align__(16) float sh[2][IN0][NB];

    const int tid = threadIdx.x;
    const int ct  = blockIdx.x & (NCTA - 1);
    const int t0  = (int)(blockIdx.x >> 7) * TCH;
    const int b0  = ct * NB;

    const int g = (tid < GG) ? tid : (GG - 1);
    unsigned long long wd[IN0], bgd;
    if (tid < 224) {
#pragma unroll
        for (int k = 0; k < IN0; k++) DUP2(wd[k], Wih[g * IN0 + k]);
        DUP2(bgd, bih[g] + bhh[g]);
    }

    const int sk = tid >> 3, sb = tid & 7;           // stager: tid < 56
    const bool stager = (tid < IN0 * NB);

    if (stager)
        sh[0][sk][sb] = x[(size_t)(b0 + sb) * TT * IN0 + (size_t)t0 * IN0 + sk];
    __syncthreads();

    int buf = 0;
    for (int t = t0; t < t0 + TCH; t++) {
        const bool hn = (t + 1 < t0 + TCH);
        float pf = 0.0f;
        if (stager && hn)
            pf = x[(size_t)(b0 + sb) * TT * IN0 + (size_t)(t + 1) * IN0 + sk];

        if (tid < 224) {
            unsigned long long a[4] = {bgd, bgd, bgd, bgd};
#pragma unroll
            for (int k = 0; k < IN0; k++) {
                ulonglong2 v0 = *(const ulonglong2*)&sh[buf][k][0];
                ulonglong2 v1 = *(const ulonglong2*)&sh[buf][k][4];
                FMA2(a[0], wd[k], v0.x);
                FMA2(a[1], wd[k], v0.y);
                FMA2(a[2], wd[k], v1.x);
                FMA2(a[3], wd[k], v1.y);
            }
            if (tid < GG) {
                size_t base = (((size_t)t * NCTA + ct) * GG + g) * NB;
                ulonglong2 o0; o0.x = a[0]; o0.y = a[1];
                ulonglong2 o1; o1.x = a[2]; o1.y = a[3];
                *(ulonglong2*)&xp[base]     = o0;
                *(ulonglong2*)&xp[base + 4] = o1;
            }
        }
        if (stager && hn) sh[buf ^ 1][sk][sb] = pf;
        __syncthreads();
        buf ^= 1;
    }
}

// ---------------------------------------------------------------------------
// Fused layer: unified compute (warps 0-13: out = W . h(t-1) + init) +
// xp(t+1) prefetch (warps 14-15). Gate role: W=Whh, init=xp(t) (has bias),
// out->sh_g. xp role: W=Wih_next, init=bias_next, out->xp_next (t-1).
// ---------------------------------------------------------------------------
__global__ void __launch_bounds__(512, 1) lstm_fused_kernel(
    const float* __restrict__ xp_cur,
    float* __restrict__ xp_next,
    int has_next,
    const float* __restrict__ Wih_next,  // [GG][HH]
    const float* __restrict__ bih_next,
    const float* __restrict__ bhh_next,
    const float* __restrict__ Whh)       // [GG][HH]
{
    __shared__ __align__(16) float sh_h[HH][NB];       // h(t-1)
    __shared__ __align__(16) float sh_g[GG][NB];       // gates
    __shared__ __align__(16) float sh_xp[2][GG][NB];   // staged xp (w/ bias)

    const int tid = threadIdx.x;
    const int ct  = blockIdx.x;
    const int b0  = ct * NB;

    const bool is_comp = (tid < 448);
    const bool is_gate = (tid < 224);
    const int  slot    = is_gate ? tid : (tid - 224);      // 0..223 per role
    const int  g       = (slot < GG) ? slot : (GG - 1);
    const bool live    = (slot < GG);
    const int  ldx     = tid - 448;                         // loaders: 0..63

    // ---- unified weight array (single physical frame for both roles)
    unsigned long long w[HH];
    unsigned long long initd = 0ull;   // xp role: dup'd bias_next
    if (is_comp) {
        const float* __restrict__ Wsrc = is_gate ? Whh : Wih_next;
#pragma unroll
        for (int k = 0; k < HH; k++) DUP2(w[k], Wsrc[g * HH + k]);
        if (!is_gate) DUP2(initd, bih_next[g] + bhh_next[g]);
    }

    // ---- update-thread state: tid<200 owns (jj, rows bu and bu+4)
    const int jj = tid >> 2;
    const int bu = tid & 3;
    float c0 = 0.0f, c1 = 0.0f;

    // ---- init: h0 = 0; stage xp(t=0)
    for (int i = tid; i < HH * NB; i += 512)
        (&sh_h[0][0])[i] = 0.0f;
    {
        const ulonglong2* src = (const ulonglong2*)
            &xp_cur[(((size_t)0 * NCTA + ct) * GG) * NB];
        ulonglong2* dst = (ulonglong2*)&sh_xp[0][0][0];
        for (int i = tid; i < GG * NB / 4; i += 512) dst[i] = src[i];
    }
    __syncthreads();

    int buf = 0;
    for (int t = 0; t < TT; t++) {
        // =========== phase A ===============================================
        ulonglong2 pf[NLD];
        if (is_comp) {
            const bool active = is_gate || (has_next && t > 0);
            if (active) {
                unsigned long long a0, a1, a2, a3;
                if (is_gate) {
                    ulonglong2 x01 = *(const ulonglong2*)&sh_xp[buf][g][0];
                    ulonglong2 x23 = *(const ulonglong2*)&sh_xp[buf][g][4];
                    a0 = x01.x; a1 = x01.y; a2 = x23.x; a3 = x23.y;
                } else {
                    a0 = initd; a1 = initd; a2 = initd; a3 = initd;
                }
#pragma unroll
                for (int k = 0; k < HH; k++) {
                    ulonglong2 h0 = *(const ulonglong2*)&sh_h[k][0];
                    ulonglong2 h1 = *(const ulonglong2*)&sh_h[k][4];
                    FMA2(a0, w[k], h0.x);
                    FMA2(a1, w[k], h0.y);
                    FMA2(a2, w[k], h1.x);
                    FMA2(a3, w[k], h1.y);
                }
                if (live) {
                    ulonglong2 o0; o0.x = a0; o0.y = a1;
                    ulonglong2 o1; o1.x = a2; o1.y = a3;
                    if (is_gate) {
                        *(ulonglong2*)&sh_g[g][0] = o0;
                        *(ulonglong2*)&sh_g[g][4] = o1;
                    } else {
                        size_t base =
                            (((size_t)(t - 1) * NCTA + ct) * GG + g) * NB;
                        *(ulonglong2*)&xp_next[base]     = o0;
                        *(ulonglong2*)&xp_next[base + 4] = o1;
                    }
                }
            }
        } else {
            // loaders: fetch xp(t+1) from global (ALL 400 ulonglong2)
            if (t + 1 < TT) {
                const ulonglong2* src = (const ulonglong2*)
                    &xp_cur[(((size_t)(t + 1) * NCTA + ct) * GG) * NB];
#pragma unroll
                for (int j = 0; j < NLD; j++) {
                    int i = ldx + j * 64;
                    if (i < GG * NB / 4) pf[j] = src[i];
                }
            }
        }
        __syncthreads();

        // =========== phase B: cell update + park prefetched xp =============
        if (tid < GG) {
#pragma unroll
            for (int q = 0; q < 2; q++) {
                int b = bu + 4 * q;
                float ig = sigmf(sh_g[jj][b]);
                float fg = sigmf(sh_g[HH + jj][b]);
                float gg = tanhfast(sh_g[2 * HH + jj][b]);
                float og = sigmf(sh_g[3 * HH + jj][b]);
                float& c = q ? c1 : c0;
                c = fg * c + ig * gg;
                float h = og * tanhfast(c);
                sh_h[jj][b] = h;
                if (t == TT - 1) g_hlast[(b0 + b) * HH + jj] = h;
            }
        } else if (!is_comp && t + 1 < TT) {
            ulonglong2* dst = (ulonglong2*)&sh_xp[buf ^ 1][0][0];
#pragma unroll
            for (int j = 0; j < NLD; j++) {
                int i = ldx + j * 64;
                if (i < GG * NB / 4) dst[i] = pf[j];
            }
        }
        __syncthreads();
        buf ^= 1;
    }

    // =========== epilogue: xp_next for h(TT-1) =============================
    if (is_comp && !is_gate && has_next) {
        unsigned long long a0 = initd, a1 = initd, a2 = initd, a3 = initd;
#pragma unroll
        for (int k = 0; k < HH; k++) {
            ulonglong2 h0 = *(const ulonglong2*)&sh_h[k][0];
            ulonglong2 h1 = *(const ulonglong2*)&sh_h[k][4];
            FMA2(a0, w[k], h0.x);
            FMA2(a1, w[k], h0.y);
            FMA2(a2, w[k], h1.x);
            FMA2(a3, w[k], h1.y);
        }
        if (live) {
            size_t base = (((size_t)(TT - 1) * NCTA + ct) * GG + g) * NB;
            ulonglong2 o0; o0.x = a0; o0.y = a1;
            ulonglong2 o1; o1.x = a2; o1.y = a3;
            *(ulonglong2*)&xp_next[base]     = o0;
            *(ulonglong2*)&xp_next[base + 4] = o1;
        }
    }
}

// ---------------------------------------------------------------------------
__global__ void fc_head_kernel(const float* __restrict__ W1,
                               const float* __restrict__ b1,
                               const float* __restrict__ W2,
                               const float* __restrict__ b2,
                               float* __restrict__ out)
{
    __shared__ float sW1[FC1 * HH];
    __shared__ float sW2[FC1];
    __shared__ float sb1[FC1];

    int tid = threadIdx.x;
    for (int i = tid; i < FC1 * HH; i += 256) sW1[i] = W1[i];
    if (tid < FC1) { sW2[tid] = W2[tid]; sb1[tid] = b1[tid]; }
    __syncthreads();

    int b = blockIdx.x * blockDim.x + tid;
    if (b < BB) {
        const float* h = &g_hlast[b * HH];
        float hreg[HH];
#pragma unroll
        for (int k = 0; k < HH; k++) hreg[k] = h[k];
        float o = b2[0];
#pragma unroll
        for (int j = 0; j < FC1; j++) {
            float a = sb1[j];
#pragma unroll
            for (int k = 0; k < HH; k++) a += sW1[j * HH + k] * hreg[k];
            o += sW2[j] * fmaxf(a, 0.0f);
        }
        out[b] = o;
    }
}

// ---------------------------------------------------------------------------
extern "C" void kernel_launch(void* const* d_in, const int* in_sizes, int n_in,
                              void* d_out, int out_size)
{
    const float* x    = (const float*)d_in[0];
    const float* Wih0 = (const float*)d_in[1];
    const float* Whh0 = (const float*)d_in[2];
    const float* bih0 = (const float*)d_in[3];
    const float* bhh0 = (const float*)d_in[4];
    const float* Wih1 = (const float*)d_in[5];
    const float* Whh1 = (const float*)d_in[6];
    const float* bih1 = (const float*)d_in[7];
    const float* bhh1 = (const float*)d_in[8];
    const float* Wih2 = (const float*)d_in[9];
    const float* Whh2 = (const float*)d_in[10];
    const float* bih2 = (const float*)d_in[11];
    const float* bhh2 = (const float*)d_in[12];
    const float* Wih3 = (const float*)d_in[13];
    const float* Whh3 = (const float*)d_in[14];
    const float* bih3 = (const float*)d_in[15];
    const float* bhh3 = (const float*)d_in[16];
    const float* W1   = (const float*)d_in[17];
    const float* b1   = (const float*)d_in[18];
    const float* W2   = (const float*)d_in[19];
    const float* b2   = (const float*)d_in[20];
    float* out = (float*)d_out;

    static float* xpA = nullptr;
    static float* xpB = nullptr;
    if (!xpA) cudaGetSymbolAddress((void**)&xpA, g_xpA);
    if (!xpB) cudaGetSymbolAddress((void**)&xpB, g_xpB);

    // layer-0 xp from external input (includes layer-0 bias)
    xp0_gemm_kernel<<<NCTA * (TT / 64), 256>>>(x, Wih0, bih0, bhh0, xpA);

    // fused layers: recurrence + next-layer xp production
    lstm_fused_kernel<<<NCTA, 512>>>(xpA, xpB, 1, Wih1, bih1, bhh1, Whh0);
    lstm_fused_kernel<<<NCTA, 512>>>(xpB, xpA, 1, Wih2, bih2, bhh2, Whh1);
    lstm_fused_kernel<<<NCTA, 512>>>(xpA, xpB, 1, Wih3, bih3, bhh3, Whh2);
    lstm_fused_kernel<<<NCTA, 512>>>(xpB, xpA, 0, Whh3, bih3, bhh3, Whh3);

    fc_head_kernel<<<(BB + 255) / 256, 256>>>(W1, b1, W2, b2, out);
}